// round 13
// baseline (speedup 1.0000x reference)
#include <cuda_runtime.h>
#include <cuda_bf16.h>
#include <stdint.h>
#include <math.h>

#define FF 32
#define BB 2048
#define KK 64
#define HH 64
#define NPAIR 496
#define NTHREADS 256
#define SLOTS 512
#define VSTRIDE 66   // bf16 elems per sV row: 132B -> conflict-free row banking
#define BPC 2        // batch rows per CTA

__device__ __align__(16) __nv_bfloat16 gWb[KK * HH];  // swizzled bf16 at_w
__device__ __align__(16) unsigned      gPij[SLOTS];   // (rowOffJ<<16)|rowOffI

__device__ __forceinline__ void ldsm_x4_trans(unsigned& r0, unsigned& r1,
                                              unsigned& r2, unsigned& r3,
                                              unsigned addr)
{
    asm volatile(
        "ldmatrix.sync.aligned.m8n8.x4.trans.shared.b16 {%0,%1,%2,%3}, [%4];\n"
        : "=r"(r0), "=r"(r1), "=r"(r2), "=r"(r3) : "r"(addr));
}

__device__ __forceinline__ void mma_bf16_16x8x16(float* c,
                                                 unsigned a0, unsigned a1,
                                                 unsigned a2, unsigned a3,
                                                 unsigned b0, unsigned b1)
{
    asm volatile(
        "mma.sync.aligned.m16n8k16.row.col.f32.bf16.bf16.f32 "
        "{%0,%1,%2,%3}, {%4,%5,%6,%7}, {%8,%9}, {%0,%1,%2,%3};\n"
        : "+f"(c[0]), "+f"(c[1]), "+f"(c[2]), "+f"(c[3])
        : "r"(a0), "r"(a1), "r"(a2), "r"(a3), "r"(b0), "r"(b1));
}

__device__ __forceinline__ unsigned hmul2u(unsigned a, unsigned b)
{
    __nv_bfloat162 r = __hmul2(*(__nv_bfloat162*)&a, *(__nv_bfloat162*)&b);
    return *(unsigned*)&r;
}

// One-shot per-launch precompute of block-invariant tables.
__global__ void afm_init(const float* __restrict__ at_w)
{
    int idx = blockIdx.x * blockDim.x + threadIdx.x;
    if (idx < KK * HH) {
        int k = idx >> 6, h = idx & 63;
        int chunk = (h >> 3) ^ (k & 7);
        gWb[k * 64 + chunk * 8 + (h & 7)] = __float2bfloat16(at_w[idx]);
    }
    if (idx < SLOTS) {
        unsigned v = 0;
        if (idx < NPAIR) {
            int i = 0, rem = idx;
            while (rem >= FF - 1 - i) { rem -= FF - 1 - i; i++; }
            int j = i + 1 + rem;
            v = ((unsigned)(j * VSTRIDE) << 16) | (unsigned)(i * VSTRIDE);
        }
        gPij[idx] = v;
    }
}

__global__ __launch_bounds__(NTHREADS, 4) void afm_kernel(
    const int* __restrict__ x, const float* __restrict__ emb,
    const float* __restrict__ at_b,
    const float* __restrict__ at_h, const float* __restrict__ pvec,
    const float* __restrict__ w0, const float* __restrict__ w1,
    float* __restrict__ out)
{
    __shared__ __align__(16) __nv_bfloat16 sVb[BPC][FF * VSTRIDE]; // 2 x 4.1 KB
    __shared__ __align__(16) __nv_bfloat16 sWb[KK * HH];           // 8 KB, swizzled
    __shared__ float sAth[HH];
    __shared__ float sAb[HH];
    __shared__ float sPooled[BPC][KK];
    __shared__ __align__(16) unsigned sPij[SLOTS];
    __shared__ int   sX[BPC][FF];
    __shared__ float sFm1[BPC];

    const int b0  = blockIdx.x * BPC;
    const int tid = threadIdx.x;
    const int w   = tid >> 5;
    const int L   = tid & 31;

    if (tid < BPC * FF) sX[tid >> 5][tid & 31] = x[(tid & 31) * BB + b0 + (tid >> 5)];
    if (tid < KK) {
        sPooled[0][tid] = 0.f;
        sPooled[1][tid] = 0.f;
        sAth[tid]       = at_h[tid];
        sAb[tid]        = at_b[tid];
    }
    // vectorized copies of precomputed tables (L2-resident)
    ((uint2*)sPij)[tid] = ((const uint2*)gPij)[tid];
    ((uint4*)sWb)[tid]       = ((const uint4*)gWb)[tid];
    ((uint4*)sWb)[tid + 256] = ((const uint4*)gWb)[tid + 256];
    __syncthreads();

    // gather embedding rows for both batches -> bf16 (coalesced along k)
    for (int idx = tid; idx < BPC * FF * KK; idx += NTHREADS) {
        int bi = idx >> 11, f = (idx >> 6) & 31, k = idx & 63;
        sVb[bi][f * VSTRIDE + k] = __float2bfloat16(emb[(long)sX[bi][f] * KK + k]);
    }
    __syncthreads();

    // first-order FM parts (warp 0 -> batch 0, warp 1 -> batch 1)
    if (w < BPC) {
        float v = w1[sX[w][L]];
        #pragma unroll
        for (int off = 16; off; off >>= 1) v += __shfl_xor_sync(0xffffffffu, v, off);
        if (L == 0) sFm1[w] = v + w0[0];
    }

    const unsigned swb_base = (unsigned)__cvta_generic_to_shared(sWb);
    const int qr  = L >> 2;        // 0..7 fragment row within 8
    const int qc2 = (L & 3) << 1;  // 0,2,4,6 fragment col pair
    const int sub = L >> 3;        // ldmatrix sub-block 0..3
    const int lr  = L & 7;

    // hoisted ldsm addresses: maddr(ks,tp) = base_tp[tp] + ks*2048
    unsigned base_tp[4];
    {
        unsigned row_base = swb_base + (unsigned)((((sub & 1) << 3) + lr) * 128);
        #pragma unroll
        for (int tp = 0; tp < 4; tp++)
            base_tp[tp] = row_base
                        + (unsigned)((((tp << 1) + (sub >> 1)) ^ lr) << 4);
    }

    // ---- per-batch: MMA + fused epilogue/pooling --------------------------
    #pragma unroll 1
    for (int bi = 0; bi < BPC; bi++) {
        const __nv_bfloat16* const vb = sVb[bi];

        // in-register pooled accumulators:
        // pk[ks][0]=k0, [1]=k0+1, [2]=k0+8, [3]=k0+9, k0 = ks*16 + qc2
        float pk[4][4];
        #pragma unroll
        for (int ks = 0; ks < 4; ks++)
            pk[ks][0] = pk[ks][1] = pk[ks][2] = pk[ks][3] = 0.f;

        #pragma unroll 1
        for (int it = 0; it < 4; it++) {
            const int mbase = (w * 4 + it) << 4;      // 16 pairs per m-tile
            const int p0 = mbase + qr, p1 = p0 + 8;
            const unsigned pij0 = sPij[p0], pij1 = sPij[p1];
            const int eI0 = pij0 & 0xffffu, eJ0 = pij0 >> 16;
            const int eI1 = pij1 & 0xffffu, eJ1 = pij1 >> 16;

            // preload all A fragments for this m-tile (16 regs) == VV values
            unsigned fa[4][4];
            #pragma unroll
            for (int ks = 0; ks < 4; ks++) {
                const int k0 = (ks << 4) + qc2;
                fa[ks][0] = hmul2u(*(const unsigned*)&vb[eI0 + k0],
                                   *(const unsigned*)&vb[eJ0 + k0]);
                fa[ks][1] = hmul2u(*(const unsigned*)&vb[eI1 + k0],
                                   *(const unsigned*)&vb[eJ1 + k0]);
                fa[ks][2] = hmul2u(*(const unsigned*)&vb[eI0 + k0 + 8],
                                   *(const unsigned*)&vb[eJ0 + k0 + 8]);
                fa[ks][3] = hmul2u(*(const unsigned*)&vb[eI1 + k0 + 8],
                                   *(const unsigned*)&vb[eJ1 + k0 + 8]);
            }

            float s0 = 0.f, s1 = 0.f;
            #pragma unroll
            for (int tp = 0; tp < 4; tp++) {
                float acc2[2][4];
                #pragma unroll
                for (int u = 0; u < 2; u++)
                    acc2[u][0] = acc2[u][1] = acc2[u][2] = acc2[u][3] = 0.f;

                #pragma unroll
                for (int ks = 0; ks < 4; ks++) {
                    unsigned maddr = base_tp[tp] + (unsigned)(ks << 11);
                    unsigned fb0, fb1, fb2, fb3;
                    ldsm_x4_trans(fb0, fb1, fb2, fb3, maddr);
                    mma_bf16_16x8x16(acc2[0], fa[ks][0], fa[ks][1], fa[ks][2], fa[ks][3], fb0, fb1);
                    mma_bf16_16x8x16(acc2[1], fa[ks][0], fa[ks][1], fa[ks][2], fa[ks][3], fb2, fb3);
                }

                #pragma unroll
                for (int u = 0; u < 2; u++) {
                    int h0 = (((tp << 1) + u) << 3) + qc2;
                    float2 ab = *(const float2*)&sAb[h0];
                    float2 ah = *(const float2*)&sAth[h0];
                    s0 += fmaxf(acc2[u][0] + ab.x, 0.f) * ah.x
                        + fmaxf(acc2[u][1] + ab.y, 0.f) * ah.y;
                    s1 += fmaxf(acc2[u][2] + ab.x, 0.f) * ah.x
                        + fmaxf(acc2[u][3] + ab.y, 0.f) * ah.y;
                }
            }

            // quad reduce -> every lane has full scores for p0, p1
            s0 += __shfl_xor_sync(0xffffffffu, s0, 1);
            s0 += __shfl_xor_sync(0xffffffffu, s0, 2);
            s1 += __shfl_xor_sync(0xffffffffu, s1, 1);
            s1 += __shfl_xor_sync(0xffffffffu, s1, 2);
            s0 = (p0 < NPAIR) ? s0 : 0.f;
            s1 = (p1 < NPAIR) ? s1 : 0.f;

            // fused pooling straight from fa regs
            #pragma unroll
            for (int ks = 0; ks < 4; ks++) {
                float2 f;
                f = __bfloat1622float2(*(__nv_bfloat162*)&fa[ks][0]);
                pk[ks][0] = fmaf(f.x, s0, pk[ks][0]);
                pk[ks][1] = fmaf(f.y, s0, pk[ks][1]);
                f = __bfloat1622float2(*(__nv_bfloat162*)&fa[ks][1]);
                pk[ks][0] = fmaf(f.x, s1, pk[ks][0]);
                pk[ks][1] = fmaf(f.y, s1, pk[ks][1]);
                f = __bfloat1622float2(*(__nv_bfloat162*)&fa[ks][2]);
                pk[ks][2] = fmaf(f.x, s0, pk[ks][2]);
                pk[ks][3] = fmaf(f.y, s0, pk[ks][3]);
                f = __bfloat1622float2(*(__nv_bfloat162*)&fa[ks][3]);
                pk[ks][2] = fmaf(f.x, s1, pk[ks][2]);
                pk[ks][3] = fmaf(f.y, s1, pk[ks][3]);
            }
        }

        // reduce pooled over the 8 qr-rows
        #pragma unroll
        for (int ks = 0; ks < 4; ks++)
            #pragma unroll
            for (int t = 0; t < 4; t++) {
                float v = pk[ks][t];
                v += __shfl_xor_sync(0xffffffffu, v, 4);
                v += __shfl_xor_sync(0xffffffffu, v, 8);
                v += __shfl_xor_sync(0xffffffffu, v, 16);
                pk[ks][t] = v;
            }
        if (L < 4) {
            #pragma unroll
            for (int ks = 0; ks < 4; ks++) {
                int k0 = (ks << 4) + (L << 1);
                atomicAdd(&sPooled[bi][k0],     pk[ks][0]);
                atomicAdd(&sPooled[bi][k0 + 1], pk[ks][1]);
                atomicAdd(&sPooled[bi][k0 + 8], pk[ks][2]);
                atomicAdd(&sPooled[bi][k0 + 9], pk[ks][3]);
            }
        }
    }
    __syncthreads();

    // finalize both batch rows (warp 0 -> b0, warp 1 -> b0+1)
    if (w < BPC) {
        float2 pv = ((const float2*)pvec)[L];
        float d = sPooled[w][2 * L] * pv.x + sPooled[w][2 * L + 1] * pv.y;
        #pragma unroll
        for (int off = 16; off; off >>= 1) d += __shfl_xor_sync(0xffffffffu, d, off);
        if (L == 0) {
            float logit = d + sFm1[w];
            out[b0 + w] = 1.f / (1.f + expf(-logit));
        }
    }
}

extern "C" void kernel_launch(void* const* d_in, const int* in_sizes, int n_in,
                              void* d_out, int out_size) {
    (void)in_sizes; (void)n_in; (void)out_size;
    const int*   x    = (const int*)  d_in[0];
    const float* emb  = (const float*)d_in[1];
    const float* at_w = (const float*)d_in[2];
    const float* at_b = (const float*)d_in[3];
    const float* at_h = (const float*)d_in[4];
    const float* pvec = (const float*)d_in[5];
    const float* w0   = (const float*)d_in[6];
    const float* w1   = (const float*)d_in[7];
    float* out = (float*)d_out;

    afm_init<<<16, 256>>>(at_w);
    afm_kernel<<<BB / BPC, NTHREADS>>>(x, emb, at_b, at_h, pvec, w0, w1, out);
}

// round 15
// speedup vs baseline: 1.2168x; 1.2168x over previous
#include <cuda_runtime.h>
#include <cuda_fp16.h>
#include <cuda_fp8.h>
#include <stdint.h>
#include <math.h>

#define FF 32
#define BB 2048
#define KK 64
#define HH 64
#define NPAIR 496
#define NTHREADS 256
#define SLOTS 512
#define VSTRIDE 66   // f16 elems per sV row (132B); 32-bit loads only (4B-aligned)

__device__ __align__(16) unsigned char gW8[HH * 64]; // fp8 W, lane-packed
__device__ __align__(16) unsigned      gPij[SLOTS];  // (rowOffJ<<16)|rowOffI

__device__ __forceinline__ unsigned short cvt_e4m3x2_f16x2(__half2 v)
{
    unsigned short r;
    asm("cvt.rn.satfinite.e4m3x2.f16x2 %0, %1;" : "=h"(r) : "r"(*(unsigned*)&v));
    return r;
}
__device__ __forceinline__ __half2 cvt_f16x2_e4m3x2(unsigned short v)
{
    unsigned r;
    asm("cvt.rn.f16x2.e4m3x2 %0, %1;" : "=r"(r) : "h"(v));
    return *(__half2*)&r;
}
__device__ __forceinline__ void mma_e4m3(float* c,
                                         unsigned a0, unsigned a1,
                                         unsigned a2, unsigned a3,
                                         unsigned b0, unsigned b1)
{
    asm volatile(
        "mma.sync.aligned.m16n8k32.row.col.f32.e4m3.e4m3.f32 "
        "{%0,%1,%2,%3}, {%4,%5,%6,%7}, {%8,%9}, {%0,%1,%2,%3};\n"
        : "+f"(c[0]), "+f"(c[1]), "+f"(c[2]), "+f"(c[3])
        : "r"(a0), "r"(a1), "r"(a2), "r"(a3), "r"(b0), "r"(b1));
}
// 32-bit loads only: rows are 4B-aligned (132B stride), NOT 8B-aligned.
__device__ __forceinline__ unsigned buildA(const __half* vh, int eI, int eJ, int koff)
{
    unsigned vi0 = *(const unsigned*)(vh + eI + koff);
    unsigned vi1 = *(const unsigned*)(vh + eI + koff + 2);
    unsigned vj0 = *(const unsigned*)(vh + eJ + koff);
    unsigned vj1 = *(const unsigned*)(vh + eJ + koff + 2);
    __half2 p0 = __hmul2(*(__half2*)&vi0, *(__half2*)&vj0);
    __half2 p1 = __hmul2(*(__half2*)&vi1, *(__half2*)&vj1);
    unsigned short lo = cvt_e4m3x2_f16x2(p0);   // bytes k0,k1
    unsigned short hi = cvt_e4m3x2_f16x2(p1);   // bytes k2,k3
    return (unsigned)lo | ((unsigned)hi << 16);
}
__device__ __forceinline__ __half2 shfl_xor_h2(__half2 v, int m)
{
    unsigned u = __shfl_xor_sync(0xffffffffu, *(unsigned*)&v, m);
    return *(__half2*)&u;
}

// One-shot precompute: fp8 W (x64, lane-packed) + pair table.
// W byte layout: (k,h) at h*64 + ((k>>2)&3)*16 + (k>>4)*4 + (k&3)
// so lane (n=h%8, c) LDS.128 at h*64+c*16 yields {b0u0, b1u0, b0u1, b1u1}.
__global__ void afm_init(const float* __restrict__ at_w)
{
    int idx = blockIdx.x * blockDim.x + threadIdx.x;
    if (idx < KK * HH) {
        int k = idx >> 6, h = idx & 63;
        int seg = k >> 4, c = (k >> 2) & 3, by = k & 3;
        __nv_fp8_storage_t f8 = __nv_cvt_float_to_fp8(
            at_w[idx] * 64.0f, __NV_SATFINITE, __NV_E4M3);
        gW8[h * 64 + c * 16 + seg * 4 + by] = (unsigned char)f8;
    }
    if (idx < SLOTS) {
        unsigned v = 0;
        if (idx < NPAIR) {
            int i = 0, rem = idx;
            while (rem >= FF - 1 - i) { rem -= FF - 1 - i; i++; }
            int j = i + 1 + rem;
            v = ((unsigned)(j * VSTRIDE) << 16) | (unsigned)(i * VSTRIDE);
        }
        gPij[idx] = v;
    }
}

__global__ __launch_bounds__(NTHREADS, 4) void afm_kernel(
    const int* __restrict__ x, const float* __restrict__ emb,
    const float* __restrict__ at_b,
    const float* __restrict__ at_h, const float* __restrict__ pvec,
    const float* __restrict__ w0, const float* __restrict__ w1,
    float* __restrict__ out)
{
    __shared__ __align__(16) __half sVh[FF * VSTRIDE];       // ~4.2 KB, V*16
    __shared__ __align__(16) unsigned char sW8[HH * 64];     // 4 KB fp8 W*64
    __shared__ float sAth[HH];
    __shared__ float sAb[HH];                                // bias * 2^14
    __shared__ float sPooled[KK];
    __shared__ __align__(16) unsigned sPij[SLOTS];
    __shared__ int   sX[FF];
    __shared__ float sFm1;

    const int b   = blockIdx.x;
    const int tid = threadIdx.x;
    const int w   = tid >> 5;
    const int L   = tid & 31;
    const int c   = L & 3;
    const int qr  = L >> 2;

    if (tid < FF) sX[tid] = x[tid * BB + b];
    if (tid < KK) {
        sPooled[tid] = 0.f;
        sAth[tid]    = at_h[tid];
        sAb[tid]     = at_b[tid] * 16384.0f;   // 2^14 pre-scale
    }
    ((uint2*)sPij)[tid] = ((const uint2*)gPij)[tid];
    ((uint4*)sW8)[tid]  = ((const uint4*)gW8)[tid];   // 4 KB = 256 uint4
    __syncthreads();

    // gather embedding rows -> f16 * 16 (coalesced along k)
    for (int idx = tid; idx < FF * KK; idx += NTHREADS) {
        int f = idx >> 6, k = idx & 63;
        sVh[f * VSTRIDE + k] = __float2half(emb[(long)sX[f] * KK + k] * 16.0f);
    }
    __syncthreads();

    // first-order FM part
    if (w == 0) {
        float v = w1[sX[L]];
        #pragma unroll
        for (int off = 16; off; off >>= 1) v += __shfl_xor_sync(0xffffffffu, v, off);
        if (L == 0) sFm1 = v + w0[0];
    }

    const __half* const vh = sVh;
    const unsigned char* const wb = sW8 + (qr << 6) + (c << 4); // lane B base
    const int kb = c << 2;  // 4c

    // half2 pooled accumulators: pk2[seg*2+r] = {k, k+1}, k = 4c+16seg+2r
    __half2 pk2[8];
    #pragma unroll
    for (int t = 0; t < 8; t++) pk2[t] = __float2half2_rn(0.f);

    // ---- MMA + fused epilogue/pooling -------------------------------------
    #pragma unroll 1
    for (int it = 0; it < 4; it++) {
        const int mbase = (w * 4 + it) << 4;
        const int p0 = mbase + qr, p1 = p0 + 8;
        const unsigned pij0 = sPij[p0], pij1 = sPij[p1];
        const int eI0 = pij0 & 0xffffu, eJ0 = pij0 >> 16;
        const int eI1 = pij1 & 0xffffu, eJ1 = pij1 >> 16;

        // A fragments (fp8): fa[u][0]=p0 k, [1]=p1 k, [2]=p0 k+16, [3]=p1 k+16
        unsigned fa[2][4];
        #pragma unroll
        for (int u = 0; u < 2; u++) {
            int k0 = kb + (u << 5);
            fa[u][0] = buildA(vh, eI0, eJ0, k0);
            fa[u][1] = buildA(vh, eI1, eJ1, k0);
            fa[u][2] = buildA(vh, eI0, eJ0, k0 + 16);
            fa[u][3] = buildA(vh, eI1, eJ1, k0 + 16);
        }

        float s0 = 0.f, s1 = 0.f;
        #pragma unroll
        for (int nt = 0; nt < 8; nt++) {
            uint4 bb = *(const uint4*)(wb + (nt << 9));   // 4 B regs, 1 LDS.128
            float acc[4] = {0.f, 0.f, 0.f, 0.f};
            mma_e4m3(acc, fa[0][0], fa[0][1], fa[0][2], fa[0][3], bb.x, bb.y);
            mma_e4m3(acc, fa[1][0], fa[1][1], fa[1][2], fa[1][3], bb.z, bb.w);

            int h0 = (nt << 3) + (c << 1);
            float2 ab = *(const float2*)&sAb[h0];
            float2 ah = *(const float2*)&sAth[h0];
            s0 += fmaxf(acc[0] + ab.x, 0.f) * ah.x
                + fmaxf(acc[1] + ab.y, 0.f) * ah.y;
            s1 += fmaxf(acc[2] + ab.x, 0.f) * ah.x
                + fmaxf(acc[3] + ab.y, 0.f) * ah.y;
        }
        // descale 2^-14, quad reduce, mask padded slots
        s0 += __shfl_xor_sync(0xffffffffu, s0, 1);
        s0 += __shfl_xor_sync(0xffffffffu, s0, 2);
        s1 += __shfl_xor_sync(0xffffffffu, s1, 1);
        s1 += __shfl_xor_sync(0xffffffffu, s1, 2);
        s0 = (p0 < NPAIR) ? s0 * 6.103515625e-05f : 0.f;
        s1 = (p1 < NPAIR) ? s1 * 6.103515625e-05f : 0.f;

        // fused pooling from fp8 A regs (VV*256), accumulate in half2
        __half2 s0h = __half2half2(__float2half_rn(s0));
        __half2 s1h = __half2half2(__float2half_rn(s1));
        #pragma unroll
        for (int u = 0; u < 2; u++) {
            int sA = (u << 1) << 1;        // pk index base for seg 2u
            int sB = ((u << 1) + 1) << 1;  // seg 2u+1
            pk2[sA]     = __hfma2(cvt_f16x2_e4m3x2((unsigned short)(fa[u][0] & 0xffffu)), s0h, pk2[sA]);
            pk2[sA + 1] = __hfma2(cvt_f16x2_e4m3x2((unsigned short)(fa[u][0] >> 16)),     s0h, pk2[sA + 1]);
            pk2[sA]     = __hfma2(cvt_f16x2_e4m3x2((unsigned short)(fa[u][1] & 0xffffu)), s1h, pk2[sA]);
            pk2[sA + 1] = __hfma2(cvt_f16x2_e4m3x2((unsigned short)(fa[u][1] >> 16)),     s1h, pk2[sA + 1]);
            pk2[sB]     = __hfma2(cvt_f16x2_e4m3x2((unsigned short)(fa[u][2] & 0xffffu)), s0h, pk2[sB]);
            pk2[sB + 1] = __hfma2(cvt_f16x2_e4m3x2((unsigned short)(fa[u][2] >> 16)),     s0h, pk2[sB + 1]);
            pk2[sB]     = __hfma2(cvt_f16x2_e4m3x2((unsigned short)(fa[u][3] & 0xffffu)), s1h, pk2[sB]);
            pk2[sB + 1] = __hfma2(cvt_f16x2_e4m3x2((unsigned short)(fa[u][3] >> 16)),     s1h, pk2[sB + 1]);
        }
    }

    // reduce pooled over qr lanes, then atomics from lanes 0-3
    #pragma unroll
    for (int t = 0; t < 8; t++) {
        __half2 v = pk2[t];
        v = __hadd2(v, shfl_xor_h2(v, 4));
        v = __hadd2(v, shfl_xor_h2(v, 8));
        v = __hadd2(v, shfl_xor_h2(v, 16));
        pk2[t] = v;
    }
    if (L < 4) {
        #pragma unroll
        for (int s = 0; s < 4; s++)
            #pragma unroll
            for (int r = 0; r < 2; r++) {
                float2 f = __half22float2(pk2[s * 2 + r]);
                int k0 = (L << 2) + (s << 4) + (r << 1);
                atomicAdd(&sPooled[k0],     f.x);
                atomicAdd(&sPooled[k0 + 1], f.y);
            }
    }
    __syncthreads();

    if (w == 0) {
        float2 pv = ((const float2*)pvec)[L];
        float d = sPooled[2 * L] * pv.x + sPooled[2 * L + 1] * pv.y;
        #pragma unroll
        for (int off = 16; off; off >>= 1) d += __shfl_xor_sync(0xffffffffu, d, off);
        if (L == 0) {
            float logit = d * 0.00390625f + sFm1;   // 2^-8 descale
            out[b] = 1.f / (1.f + expf(-logit));
        }
    }
}

extern "C" void kernel_launch(void* const* d_in, const int* in_sizes, int n_in,
                              void* d_out, int out_size) {
    (void)in_sizes; (void)n_in; (void)out_size;
    const int*   x    = (const int*)  d_in[0];
    const float* emb  = (const float*)d_in[1];
    const float* at_w = (const float*)d_in[2];
    const float* at_b = (const float*)d_in[3];
    const float* at_h = (const float*)d_in[4];
    const float* pvec = (const float*)d_in[5];
    const float* w0   = (const float*)d_in[6];
    const float* w1   = (const float*)d_in[7];
    float* out = (float*)d_out;

    afm_init<<<16, 256>>>(at_w);
    afm_kernel<<<BB, NTHREADS>>>(x, emb, at_b, at_h, pvec, w0, w1, out);
}